// round 6
// baseline (speedup 1.0000x reference)
#include <cuda_runtime.h>

// Problem constants
#define BATCH 1024
#define CCH   3
#define HH    224
#define WW    220
#define PROWS 4
#define PCOLS 5
#define NPATCH 20
#define HID   32
#define PH    56          // HH / PROWS
#define PW    44          // WW / PCOLS
#define V4_PER_ROW   55   // WW / 4 (full stripe row)
#define V4_PER_STRIPE (PH * V4_PER_ROW)   // 3080 float4 per (b,c,pr) stripe
#define MEAN_DIV (CCH * PH * PW)          // 7392

// Per-(b, pr, pc, c) partial patch sums. Written by kernel1, read by kernel2.
__device__ float g_part[BATCH * PROWS * PCOLS * CCH];
// Scratch for contribs if the output buffer doesn't hold them
__device__ float g_contribs[BATCH * NPATCH];

// Kernel 1: dense contiguous sweep of one (b, c, pr) stripe (49,280 B),
// accumulating 5 patch-column partial sums.
__global__ __launch_bounds__(256) void stripe_sum_kernel(
    const float* __restrict__ x,
    float* __restrict__ part)
{
    const int blk = blockIdx.x;              // ((b*3 + c)*4 + pr), pr fastest
    const int pr  = blk & 3;
    const int bc  = blk >> 2;                // b*3 + c
    const int c   = bc % 3;
    const int b   = bc / 3;
    const int tid = threadIdx.x;

    const float4* region = reinterpret_cast<const float4*>(
        x + ((size_t)bc * HH + (size_t)pr * PH) * WW);

    float a0 = 0.f, a1 = 0.f, a2 = 0.f, a3 = 0.f, a4 = 0.f;

    #pragma unroll 4
    for (int i = tid; i < V4_PER_STRIPE; i += 256) {
        float4 d = region[i];
        float s = (d.x + d.y) + (d.z + d.w);
        int k  = i % V4_PER_ROW;     // float4 index within row [0,55)
        int pc = k / 11;             // patch column [0,5)
        if      (pc == 0) a0 += s;
        else if (pc == 1) a1 += s;
        else if (pc == 2) a2 += s;
        else if (pc == 3) a3 += s;
        else              a4 += s;
    }

    // Block-reduce the 5 accumulators
    float accs[5] = {a0, a1, a2, a3, a4};
    __shared__ float red[5][8];
    const int lane = tid & 31;
    const int wrp  = tid >> 5;
    #pragma unroll
    for (int pc = 0; pc < 5; pc++) {
        float v = accs[pc];
        #pragma unroll
        for (int o = 16; o > 0; o >>= 1)
            v += __shfl_down_sync(0xffffffffu, v, o);
        if (lane == 0) red[pc][wrp] = v;
    }
    __syncthreads();

    if (tid < 5) {
        float s = 0.f;
        #pragma unroll
        for (int w = 0; w < 8; w++) s += red[tid][w];
        // layout: ((b*4 + pr)*5 + pc)*3 + c  ==  (b*20 + p)*3 + c
        part[((size_t)(b * PROWS + pr) * PCOLS + tid) * CCH + c] = s;
    }
}

// Kernel 2: fold channel partials -> patch mean -> scalar MLP -> contribs,
// then warp-reduce 20 contribs -> score. One 32-thread block per batch item.
__global__ __launch_bounds__(32) void mlp_score_kernel(
    const float* __restrict__ part,
    const float* __restrict__ w1,
    const float* __restrict__ b1,
    const float* __restrict__ w2,
    const float* __restrict__ b2,
    float* __restrict__ contribs,
    float* __restrict__ score)
{
    const int b = blockIdx.x;
    const int p = threadIdx.x;

    float contrib = 0.f;
    if (p < NPATCH) {
        const float* gp = part + (size_t)(b * NPATCH + p) * CCH;
        float f = ((gp[0] + gp[1]) + gp[2]) * (1.0f / (float)MEAN_DIV);

        float acc = b2[p];
        const float* w1p = w1 + p * HID;
        const float* b1p = b1 + p * HID;
        const float* w2p = w2 + p * HID;
        #pragma unroll
        for (int k = 0; k < HID; k++) {
            float h = fmaf(f, w1p[k], b1p[k]);
            h = fmaxf(h, 0.0f);
            acc = fmaf(h, w2p[k], acc);
        }
        contrib = acc;
        if (contribs != nullptr)
            contribs[b * NPATCH + p] = acc;
    }

    // warp reduce 20 contribs (lanes >= 20 carry 0)
    float s = contrib;
    #pragma unroll
    for (int o = 16; o > 0; o >>= 1)
        s += __shfl_down_sync(0xffffffffu, s, o);
    if (p == 0 && score != nullptr)
        score[b] = s;
}

extern "C" void kernel_launch(void* const* d_in, const int* in_sizes, int n_in,
                              void* d_out, int out_size)
{
    const float* x  = (const float*)d_in[0];
    const float* w1 = (const float*)d_in[1];
    const float* b1 = (const float*)d_in[2];
    const float* w2 = (const float*)d_in[3];
    const float* b2 = (const float*)d_in[4];

    float* out = (float*)d_out;
    float* score_ptr    = nullptr;
    float* contribs_ptr = nullptr;

    if (out_size == BATCH * (NPATCH + 1)) {
        score_ptr    = out;           // (score, contribs) concatenated
        contribs_ptr = out + BATCH;
    } else if (out_size == BATCH) {
        score_ptr = out;
        cudaGetSymbolAddress((void**)&contribs_ptr, g_contribs);
    } else if (out_size == BATCH * NPATCH) {
        contribs_ptr = out;
    } else {
        score_ptr    = out;
        contribs_ptr = out + BATCH;
    }

    float* part_ptr;
    cudaGetSymbolAddress((void**)&part_ptr, g_part);

    stripe_sum_kernel<<<BATCH * CCH * PROWS, 256>>>(x, part_ptr);
    mlp_score_kernel<<<BATCH, 32>>>(part_ptr, w1, b1, w2, b2,
                                    contribs_ptr, score_ptr);
}

// round 7
// speedup vs baseline: 1.1236x; 1.1236x over previous
#include <cuda_runtime.h>

// Problem constants
#define BATCH 1024
#define CCH   3
#define HH    224
#define WW    220
#define PROWS 4
#define PCOLS 5
#define NPATCH 20
#define HID   32
#define PH    56          // HH / PROWS
#define PW    44          // WW / PCOLS
#define V4_PER_ROW   55   // WW / 4 (full stripe row)
#define V4_PER_STRIPE (PH * V4_PER_ROW)   // 3080 float4 per (b,c,pr) stripe
#define MAIN_ITERS   12                   // 256*12 = 3072
#define TAIL_V4      8                    // 3080 - 3072 (all land in pc=4)
#define MEAN_DIV (CCH * PH * PW)          // 7392

// Per-(b, pr, pc, c) partial patch sums. Written by kernel1, read by kernel2.
__device__ float g_part[BATCH * PROWS * PCOLS * CCH];
// Scratch for contribs if the output buffer doesn't hold them
__device__ float g_contribs[BATCH * NPATCH];

// Kernel 1: dense contiguous sweep of one (b, c, pr) stripe (49,280 B).
// Constant-trip fully-unrolled load batch (12 independent LDG.128/thread)
// for deep memory-level parallelism, then patch-column classification.
__global__ __launch_bounds__(256) void stripe_sum_kernel(
    const float* __restrict__ x,
    float* __restrict__ part)
{
    const int blk = blockIdx.x;              // ((b*3 + c)*4 + pr), pr fastest
    const int pr  = blk & 3;
    const int bc  = blk >> 2;                // b*3 + c
    const int c   = bc % 3;
    const int b   = bc / 3;
    const int tid = threadIdx.x;

    const float4* region = reinterpret_cast<const float4*>(
        x + ((size_t)bc * HH + (size_t)pr * PH) * WW);

    // Batch all 12 loads up front: independent addresses, deep MLP.
    float4 d[MAIN_ITERS];
    #pragma unroll
    for (int u = 0; u < MAIN_ITERS; u++)
        d[u] = region[tid + u * 256];

    float a0 = 0.f, a1 = 0.f, a2 = 0.f, a3 = 0.f, a4 = 0.f;
    #pragma unroll
    for (int u = 0; u < MAIN_ITERS; u++) {
        float s = (d[u].x + d[u].y) + (d[u].z + d[u].w);
        int i  = tid + u * 256;
        int k  = i % V4_PER_ROW;     // float4 index within row [0,55)
        int pc = k / 11;             // patch column [0,5)
        if      (pc == 0) a0 += s;
        else if (pc == 1) a1 += s;
        else if (pc == 2) a2 += s;
        else if (pc == 3) a3 += s;
        else              a4 += s;
    }

    // Tail: i in [3072,3080) -> k in [47,54] -> all patch column 4.
    if (tid < TAIL_V4) {
        float4 t = region[MAIN_ITERS * 256 + tid];
        a4 += (t.x + t.y) + (t.z + t.w);
    }

    // Block-reduce the 5 accumulators
    float accs[5] = {a0, a1, a2, a3, a4};
    __shared__ float red[5][8];
    const int lane = tid & 31;
    const int wrp  = tid >> 5;
    #pragma unroll
    for (int pc = 0; pc < 5; pc++) {
        float v = accs[pc];
        #pragma unroll
        for (int o = 16; o > 0; o >>= 1)
            v += __shfl_down_sync(0xffffffffu, v, o);
        if (lane == 0) red[pc][wrp] = v;
    }
    __syncthreads();

    if (tid < 5) {
        float s = 0.f;
        #pragma unroll
        for (int w = 0; w < 8; w++) s += red[tid][w];
        // layout: ((b*4 + pr)*5 + pc)*3 + c  ==  (b*20 + p)*3 + c
        part[((size_t)(b * PROWS + pr) * PCOLS + tid) * CCH + c] = s;
    }
}

// Kernel 2: one WARP per batch item (8 warps/block, 128 blocks).
// Lanes 0..19: fold channel partials -> mean -> 32-wide MLP -> contribs.
// Then warp shuffle-reduce -> score.
__global__ __launch_bounds__(256) void mlp_score_kernel(
    const float* __restrict__ part,
    const float* __restrict__ w1,
    const float* __restrict__ b1,
    const float* __restrict__ w2,
    const float* __restrict__ b2,
    float* __restrict__ contribs,
    float* __restrict__ score)
{
    const int warp = threadIdx.x >> 5;
    const int lane = threadIdx.x & 31;
    const int b = blockIdx.x * 8 + warp;
    const int p = lane;

    float contrib = 0.f;
    if (p < NPATCH) {
        const float* gp = part + (size_t)(b * NPATCH + p) * CCH;
        float f = ((gp[0] + gp[1]) + gp[2]) * (1.0f / (float)MEAN_DIV);

        float acc = b2[p];
        const float* w1p = w1 + p * HID;
        const float* b1p = b1 + p * HID;
        const float* w2p = w2 + p * HID;
        #pragma unroll
        for (int k = 0; k < HID; k++) {
            float h = fmaf(f, w1p[k], b1p[k]);
            h = fmaxf(h, 0.0f);
            acc = fmaf(h, w2p[k], acc);
        }
        contrib = acc;
        if (contribs != nullptr)
            contribs[b * NPATCH + p] = acc;
    }

    // warp reduce 20 contribs (lanes >= 20 carry 0)
    float s = contrib;
    #pragma unroll
    for (int o = 16; o > 0; o >>= 1)
        s += __shfl_down_sync(0xffffffffu, s, o);
    if (lane == 0 && score != nullptr)
        score[b] = s;
}

extern "C" void kernel_launch(void* const* d_in, const int* in_sizes, int n_in,
                              void* d_out, int out_size)
{
    const float* x  = (const float*)d_in[0];
    const float* w1 = (const float*)d_in[1];
    const float* b1 = (const float*)d_in[2];
    const float* w2 = (const float*)d_in[3];
    const float* b2 = (const float*)d_in[4];

    float* out = (float*)d_out;
    float* score_ptr    = nullptr;
    float* contribs_ptr = nullptr;

    if (out_size == BATCH * (NPATCH + 1)) {
        score_ptr    = out;           // (score, contribs) concatenated
        contribs_ptr = out + BATCH;
    } else if (out_size == BATCH) {
        score_ptr = out;
        cudaGetSymbolAddress((void**)&contribs_ptr, g_contribs);
    } else if (out_size == BATCH * NPATCH) {
        contribs_ptr = out;
    } else {
        score_ptr    = out;
        contribs_ptr = out + BATCH;
    }

    float* part_ptr;
    cudaGetSymbolAddress((void**)&part_ptr, g_part);

    stripe_sum_kernel<<<BATCH * CCH * PROWS, 256>>>(x, part_ptr);
    mlp_score_kernel<<<BATCH / 8, 256>>>(part_ptr, w1, b1, w2, b2,
                                         contribs_ptr, score_ptr);
}